// round 1
// baseline (speedup 1.0000x reference)
#include <cuda_runtime.h>
#include <cstdint>

// Problem shape (fixed by the dataset)
#define Bq 2
#define Hh 16
#define Ss 2048
#define Dd 64
constexpr int BH = Bq * Hh;          // 32
constexpr int QT = 128;              // q rows per CTA
constexpr int KT = 128;              // k cols per tile
constexpr int NTHREADS = 256;        // 8 warps
constexpr int SQS = 68;              // padded stride for 64-wide fp32 tiles
constexpr int SUS = 132;             // padded stride for 128-wide u tile
constexpr long long OUT_ELEMS = (long long)BH * Ss * Dd;   // 4,194,304
constexpr long long ATT_ELEMS = (long long)BH * Ss * Ss;   // 134,217,728

// floats: 3*(128*68) + 128*132 + 128 = 43136 -> 172,544 bytes dynamic smem
constexpr int SMEM_FLOATS = 3 * 128 * SQS + 128 * SUS + 128;
constexpr int SMEM_BYTES  = SMEM_FLOATS * 4;

// scratch: reciprocal row sums (1/sum of exp) for the normalize pass
__device__ float g_rinv[BH * Ss];

__device__ __forceinline__ float tf32r(float x) {
    uint32_t u;
    asm("cvt.rna.tf32.f32 %0, %1;" : "=r"(u) : "f"(x));
    return __uint_as_float(u);
}

__device__ __forceinline__ void mma8(float* c, const uint32_t* a, const uint32_t* b) {
    asm volatile(
        "mma.sync.aligned.m16n8k8.row.col.f32.tf32.tf32.f32 "
        "{%0,%1,%2,%3}, {%4,%5,%6,%7}, {%8,%9}, {%0,%1,%2,%3};\n"
        : "+f"(c[0]), "+f"(c[1]), "+f"(c[2]), "+f"(c[3])
        : "r"(a[0]), "r"(a[1]), "r"(a[2]), "r"(a[3]), "r"(b[0]), "r"(b[1]));
}

extern __shared__ float smem[];

__global__ void __launch_bounds__(NTHREADS, 1)
attn_kernel(const float* __restrict__ Q, const float* __restrict__ K,
            const float* __restrict__ V, const int* __restrict__ M,
            float* __restrict__ out, float* __restrict__ att)
{
    float* sQ   = smem;                    // [128][68] tf32 bits, pre-scaled by 1/8
    float* sK   = sQ + 128 * SQS;          // [128][68] tf32 bits
    float* sV   = sK + 128 * SQS;          // [128][68] tf32 bits
    float* sU   = sV + 128 * SQS;          // [128][132] tf32 bits of exp(e)
    float* sRow = sU + 128 * SUS;          // [128] row sums -> reciprocals

    const int tid  = threadIdx.x;
    const int lane = tid & 31;
    const int warp = tid >> 5;
    const int g    = lane >> 2;            // groupID (0..7)
    const int tg   = lane & 3;             // threadID_in_group (0..3)
    const int wq   = warp >> 1;            // 0..3  (q quadrant, 32 rows)
    const int wk   = warp & 1;             // 0..1  (k half for E / d half for O)

    const int q0 = blockIdx.x * QT;
    const int bh = blockIdx.y;
    const int b  = bh >> 4;                // bh / H

    if (tid < 128) sRow[tid] = 0.f;

    // ---- load Q tile (scaled by 1/8, RNA-rounded to tf32) ----
    {
        const float* Qg = Q + ((size_t)bh * Ss + q0) * Dd;
        #pragma unroll
        for (int i = 0; i < 8; i++) {
            int idx = tid + i * NTHREADS;            // 0..2047 float4s
            int r = idx >> 4, c4 = (idx & 15) << 2;
            float4 v4 = *(const float4*)(Qg + (size_t)r * Dd + c4);
            float* d = sQ + r * SQS + c4;
            *(float4*)d = make_float4(tf32r(v4.x * 0.125f), tf32r(v4.y * 0.125f),
                                      tf32r(v4.z * 0.125f), tf32r(v4.w * 0.125f));
        }
    }

    float o[2][4][4];
    #pragma unroll
    for (int mi = 0; mi < 2; mi++)
        #pragma unroll
        for (int ni = 0; ni < 4; ni++)
            #pragma unroll
            for (int j = 0; j < 4; j++) o[mi][ni][j] = 0.f;

    float rsum[2][2] = {{0.f, 0.f}, {0.f, 0.f}};

    const float* Kg = K + (size_t)bh * Ss * Dd;
    const float* Vg = V + (size_t)bh * Ss * Dd;
    const int*   Mg = M + (size_t)b * Ss * Ss;
    float* attg = att ? (att + (size_t)bh * Ss * Ss) : nullptr;

    for (int t = 0; t < Ss / KT; t++) {
        __syncthreads();   // previous PV done -> safe to overwrite sK/sV
        // ---- load K,V tiles (tf32) ----
        {
            const float* Kt = Kg + (size_t)t * KT * Dd;
            const float* Vt = Vg + (size_t)t * KT * Dd;
            #pragma unroll
            for (int i = 0; i < 8; i++) {
                int idx = tid + i * NTHREADS;
                int r = idx >> 4, c4 = (idx & 15) << 2;
                float4 kv = *(const float4*)(Kt + (size_t)r * Dd + c4);
                float4 vv = *(const float4*)(Vt + (size_t)r * Dd + c4);
                *(float4*)(sK + r * SQS + c4) =
                    make_float4(tf32r(kv.x), tf32r(kv.y), tf32r(kv.z), tf32r(kv.w));
                *(float4*)(sV + r * SQS + c4) =
                    make_float4(tf32r(vv.x), tf32r(vv.y), tf32r(vv.z), tf32r(vv.w));
            }
        }
        __syncthreads();

        // ---- E = (Q/8) @ K^T : warp tile 32(q) x 64(k), K-dim = 64 ----
        float e[2][8][4];
        #pragma unroll
        for (int mi = 0; mi < 2; mi++)
            #pragma unroll
            for (int ni = 0; ni < 8; ni++)
                #pragma unroll
                for (int j = 0; j < 4; j++) e[mi][ni][j] = 0.f;

        #pragma unroll
        for (int dd = 0; dd < 8; dd++) {
            const int d0 = dd * 8;
            uint32_t a[2][4];
            #pragma unroll
            for (int mi = 0; mi < 2; mi++) {
                int r = (wq * 32 + mi * 16 + g) * SQS + d0 + tg;
                a[mi][0] = __float_as_uint(sQ[r]);
                a[mi][1] = __float_as_uint(sQ[r + 8 * SQS]);
                a[mi][2] = __float_as_uint(sQ[r + 4]);
                a[mi][3] = __float_as_uint(sQ[r + 8 * SQS + 4]);
            }
            #pragma unroll
            for (int ni = 0; ni < 8; ni++) {
                uint32_t bb[2];
                int rr = (wk * 64 + ni * 8 + g) * SQS + d0 + tg;
                bb[0] = __float_as_uint(sK[rr]);
                bb[1] = __float_as_uint(sK[rr + 4]);
                #pragma unroll
                for (int mi = 0; mi < 2; mi++) mma8(e[mi][ni], a[mi], bb);
            }
        }

        // ---- epilogue: u = mask ? exp(e) : 0 ; store u (gmem + sU) ; rowsum ----
        #pragma unroll
        for (int mi = 0; mi < 2; mi++) {
            const int r0l = wq * 32 + mi * 16 + g;       // local q row
            const size_t qrow0 = (size_t)(q0 + r0l);
            #pragma unroll
            for (int ni = 0; ni < 8; ni++) {
                const int cl = wk * 64 + ni * 8 + 2 * tg; // local k col (even)
                const int cg = t * KT + cl;               // global k col
                int2 m0 = *(const int2*)(Mg + qrow0 * Ss + cg);
                int2 m1 = *(const int2*)(Mg + (qrow0 + 8) * Ss + cg);
                float u0 = m0.x ? __expf(e[mi][ni][0]) : 0.f;
                float u1 = m0.y ? __expf(e[mi][ni][1]) : 0.f;
                float u2 = m1.x ? __expf(e[mi][ni][2]) : 0.f;
                float u3 = m1.y ? __expf(e[mi][ni][3]) : 0.f;
                rsum[mi][0] += u0 + u1;
                rsum[mi][1] += u2 + u3;
                if (attg) {
                    *(float2*)(attg + qrow0 * Ss + cg)       = make_float2(u0, u1);
                    *(float2*)(attg + (qrow0 + 8) * Ss + cg) = make_float2(u2, u3);
                }
                *(float2*)(sU + r0l * SUS + cl)       = make_float2(tf32r(u0), tf32r(u1));
                *(float2*)(sU + (r0l + 8) * SUS + cl) = make_float2(tf32r(u2), tf32r(u3));
            }
        }
        __syncthreads();

        // ---- O += sU(128x128) @ sV(128x64) : warp tile 32(q) x 32(d) ----
        #pragma unroll
        for (int kk = 0; kk < 16; kk++) {
            const int kb = kk * 8;
            uint32_t a[2][4];
            #pragma unroll
            for (int mi = 0; mi < 2; mi++) {
                int r = (wq * 32 + mi * 16 + g) * SUS + kb + tg;
                a[mi][0] = __float_as_uint(sU[r]);
                a[mi][1] = __float_as_uint(sU[r + 8 * SUS]);
                a[mi][2] = __float_as_uint(sU[r + 4]);
                a[mi][3] = __float_as_uint(sU[r + 8 * SUS + 4]);
            }
            #pragma unroll
            for (int ni = 0; ni < 4; ni++) {
                uint32_t bb[2];
                int cc = wk * 32 + ni * 8 + g;
                bb[0] = __float_as_uint(sV[(kb + tg) * SQS + cc]);
                bb[1] = __float_as_uint(sV[(kb + tg + 4) * SQS + cc]);
                #pragma unroll
                for (int mi = 0; mi < 2; mi++) mma8(o[mi][ni], a[mi], bb);
            }
        }
    }

    // ---- reduce row sums (4 lanes share a row; 2 k-warps share rows) ----
    #pragma unroll
    for (int mi = 0; mi < 2; mi++) {
        #pragma unroll
        for (int h = 0; h < 2; h++) {
            float v = rsum[mi][h];
            v += __shfl_xor_sync(0xffffffffu, v, 1);
            v += __shfl_xor_sync(0xffffffffu, v, 2);
            if (tg == 0) atomicAdd(&sRow[wq * 32 + mi * 16 + h * 8 + g], v);
        }
    }
    __syncthreads();
    if (tid < 128) {
        float s = sRow[tid];
        float r = (s > 0.f) ? (1.0f / s) : 0.f;   // all-masked row -> 0 (matches NaN cleanup)
        sRow[tid] = r;
        g_rinv[(size_t)bh * Ss + q0 + tid] = r;
    }
    __syncthreads();

    // ---- write O = (sum u V) / rowsum ----
    if (out) {
        float* og = out + ((size_t)bh * Ss + q0) * Dd;
        #pragma unroll
        for (int mi = 0; mi < 2; mi++) {
            const int r0l = wq * 32 + mi * 16 + g;
            const float s0 = sRow[r0l], s1 = sRow[r0l + 8];
            #pragma unroll
            for (int ni = 0; ni < 4; ni++) {
                const int cl = wk * 32 + ni * 8 + 2 * tg;
                *(float2*)(og + (size_t)r0l * Dd + cl) =
                    make_float2(o[mi][ni][0] * s0, o[mi][ni][1] * s0);
                *(float2*)(og + (size_t)(r0l + 8) * Dd + cl) =
                    make_float2(o[mi][ni][2] * s1, o[mi][ni][3] * s1);
            }
        }
    }
}

// attention[i] *= 1/rowsum  (row = i / S); float4-vectorized
__global__ void __launch_bounds__(256) norm_kernel(float* __restrict__ att)
{
    size_t i = (size_t)blockIdx.x * blockDim.x + threadIdx.x;   // float4 index
    size_t row = i >> 9;                                        // 512 float4 per row
    float r = g_rinv[row];
    float4* p = (float4*)att + i;
    float4 v = *p;
    v.x *= r; v.y *= r; v.z *= r; v.w *= r;
    *p = v;
}

extern "C" void kernel_launch(void* const* d_in, const int* in_sizes, int n_in,
                              void* d_out, int out_size)
{
    (void)in_sizes; (void)n_in;
    const float* Q = (const float*)d_in[0];
    const float* K = (const float*)d_in[1];
    const float* V = (const float*)d_in[2];
    const int*   M = (const int*)d_in[3];

    float* outp = nullptr;
    float* attp = nullptr;
    long long os = (long long)out_size;
    if (os >= OUT_ELEMS + ATT_ELEMS) {        // tuple (out, attention) flattened
        outp = (float*)d_out;
        attp = (float*)d_out + OUT_ELEMS;
    } else if (os >= ATT_ELEMS) {             // attention only
        attp = (float*)d_out;
    } else {                                  // out only
        outp = (float*)d_out;
    }

    cudaFuncSetAttribute(attn_kernel, cudaFuncAttributeMaxDynamicSharedMemorySize, SMEM_BYTES);

    dim3 grid(Ss / QT, BH);
    attn_kernel<<<grid, NTHREADS, SMEM_BYTES>>>(Q, K, V, M, outp, attp);
    if (attp) {
        unsigned nblk = (unsigned)(ATT_ELEMS / 4 / 256);   // 131072
        norm_kernel<<<nblk, 256>>>(attp);
    }
}

// round 3
// speedup vs baseline: 1.4833x; 1.4833x over previous
#include <cuda_runtime.h>
#include <cuda_fp16.h>
#include <cstdint>

// Problem shape (fixed)
#define Ss 2048
#define Dd 64
constexpr int BH  = 32;
constexpr int QT  = 128;
constexpr int KT  = 128;
constexpr int NTH = 256;          // 8 warps; warp w owns q rows 16w..16w+15
constexpr long long OUT_ELEMS = (long long)BH * Ss * Dd;
constexpr long long ATT_ELEMS = (long long)BH * Ss * (long long)Ss;

constexpr int LDH = 72;           // halves per smem row (pad: conflict-free ldmatrix)
constexpr int OFF_ROWS = 0;       // 128 floats row sums
constexpr int OFF_RINV = 512;     // 128 floats reciprocals
constexpr int OFF_Q    = 1024;
constexpr int OFF_K    = OFF_Q + 128 * LDH * 2;   // +18432
constexpr int OFF_V    = OFF_K + 128 * LDH * 2;
constexpr int SMEM_BYTES = OFF_V + 128 * LDH * 2; // 56320 B

__device__ __forceinline__ uint32_t smem_u32(const void* p) {
    uint32_t a;
    asm("{ .reg .u64 t; cvta.to.shared.u64 t, %1; cvt.u32.u64 %0, t; }" : "=r"(a) : "l"(p));
    return a;
}
__device__ __forceinline__ void ldsm4(uint32_t r[4], uint32_t a) {
    asm volatile("ldmatrix.sync.aligned.m8n8.x4.shared.b16 {%0,%1,%2,%3}, [%4];"
                 : "=r"(r[0]), "=r"(r[1]), "=r"(r[2]), "=r"(r[3]) : "r"(a) : "memory");
}
__device__ __forceinline__ void ldsm4t(uint32_t r[4], uint32_t a) {
    asm volatile("ldmatrix.sync.aligned.m8n8.x4.trans.shared.b16 {%0,%1,%2,%3}, [%4];"
                 : "=r"(r[0]), "=r"(r[1]), "=r"(r[2]), "=r"(r[3]) : "r"(a) : "memory");
}
__device__ __forceinline__ void mma16816(float c[4], const uint32_t a[4], uint32_t b0, uint32_t b1) {
    asm volatile(
        "mma.sync.aligned.m16n8k16.row.col.f32.f16.f16.f32 "
        "{%0,%1,%2,%3}, {%4,%5,%6,%7}, {%8,%9}, {%0,%1,%2,%3};"
        : "+f"(c[0]), "+f"(c[1]), "+f"(c[2]), "+f"(c[3])
        : "r"(a[0]), "r"(a[1]), "r"(a[2]), "r"(a[3]), "r"(b0), "r"(b1));
}
__device__ __forceinline__ uint32_t packh2(float x, float y) {
    __half2 h = __floats2half2_rn(x, y);
    return *(uint32_t*)&h;
}

// load a 128x64 fp32 tile -> smem half [128][LDH], optional scale
__device__ __forceinline__ void load_tile(const float* __restrict__ g, char* s, int off,
                                          int tid, float scale) {
    #pragma unroll
    for (int i = 0; i < 8; i++) {
        int idx = tid + i * NTH;                 // 2048 float4
        int r = idx >> 4, c4 = (idx & 15) << 2;
        float4 v = *(const float4*)(g + (size_t)r * Dd + c4);
        uint2 u;
        u.x = packh2(v.x * scale, v.y * scale);
        u.y = packh2(v.z * scale, v.w * scale);
        *(uint2*)(s + off + (r * LDH + c4) * 2) = u;
    }
}

extern __shared__ __align__(16) char sm[];

__global__ void __launch_bounds__(NTH, 1)
attn_kernel(const float* __restrict__ Q, const float* __restrict__ K,
            const float* __restrict__ V, const int* __restrict__ M,
            float* __restrict__ out, float* __restrict__ att)
{
    const int tid  = threadIdx.x;
    const int lane = tid & 31;
    const int warp = tid >> 5;
    const int g    = lane >> 2;          // groupID 0..7
    const int tg   = lane & 3;           // thread-in-group 0..3
    const int lm   = lane >> 3;          // ldmatrix matrix id 0..3
    const int ll   = lane & 7;           // ldmatrix row-in-matrix

    const int q0 = blockIdx.x * QT;
    const int bh = blockIdx.y;
    const int b  = bh >> 4;

    const uint32_t smb = smem_u32(sm);
    float* srows = (float*)(sm + OFF_ROWS);
    float* srinv = (float*)(sm + OFF_RINV);

    const float* Qg = Q + ((size_t)bh * Ss + q0) * Dd;
    const float* Kg = K + (size_t)bh * Ss * Dd;
    const float* Vg = V + (size_t)bh * Ss * Dd;
    const int*   Mg = M + (size_t)b * Ss * (size_t)Ss;
    float* attg = att ? (att + (size_t)bh * Ss * (size_t)Ss) : nullptr;

    const int qrow = q0 + warp * 16 + g;        // thread's first q row (also +8)

    // ---- Q tile once (scaled by 1/8) ----
    load_tile(Qg, sm, OFF_Q, tid, 0.125f);

    // precomputed lane-dependent ldmatrix address pieces
    // A (Q / also layout for E's B on K): row = base + (lm&1)*8 + ll ; col = (lm>>1)*8
    const uint32_t aRow = (uint32_t)(((lm & 1) * 8 + ll) * LDH + (lm >> 1) * 8) * 2;
    // E's B on K: row = 16np + (lm>>1)*8 + ll ; col = (lm&1)*8
    const uint32_t bRow = (uint32_t)((((lm >> 1) * 8 + ll) * LDH) + (lm & 1) * 8) * 2;
    // PV's B on V (trans): row = 16kc + (lm&1)*8 + ll ; col = 8*(2np + (lm>>1))
    const uint32_t vRow = (uint32_t)(((lm & 1) * 8 + ll) * LDH + (lm >> 1) * 8) * 2;

    const uint32_t sQb = smb + OFF_Q + (uint32_t)(warp * 16 * LDH) * 2 + aRow;
    const uint32_t sKb = smb + OFF_K + bRow;
    const uint32_t sVb = smb + OFF_V + vRow;

    float c[16][4];

    // =============== PASS 1: row sums ===============
    float rs0 = 0.f, rs1 = 0.f;
    for (int t = 0; t < Ss / KT; t++) {
        __syncthreads();
        load_tile(Kg + (size_t)t * KT * Dd, sm, OFF_K, tid, 1.0f);
        __syncthreads();

        #pragma unroll
        for (int nt = 0; nt < 16; nt++)
            #pragma unroll
            for (int j = 0; j < 4; j++) c[nt][j] = 0.f;

        #pragma unroll
        for (int kc = 0; kc < 4; kc++) {
            uint32_t a[4];
            ldsm4(a, sQb + kc * 32);                       // 16kc halves * 2B
            #pragma unroll
            for (int np = 0; np < 8; np++) {
                uint32_t bf[4];
                ldsm4(bf, sKb + (uint32_t)(np * 16 * LDH) * 2 + kc * 32);
                mma16816(c[2 * np],     a, bf[0], bf[1]);
                mma16816(c[2 * np + 1], a, bf[2], bf[3]);
            }
        }

        const int* mr = Mg + (size_t)qrow * Ss + t * KT + 2 * tg;
        #pragma unroll
        for (int nt = 0; nt < 16; nt++) {
            int2 m0 = *(const int2*)(mr + 8 * nt);
            int2 m1 = *(const int2*)(mr + 8 * Ss + 8 * nt);
            rs0 += (m0.x ? __expf(c[nt][0]) : 0.f) + (m0.y ? __expf(c[nt][1]) : 0.f);
            rs1 += (m1.x ? __expf(c[nt][2]) : 0.f) + (m1.y ? __expf(c[nt][3]) : 0.f);
        }
    }
    // quad-reduce (4 lanes share each row), publish, invert
    rs0 += __shfl_xor_sync(0xffffffffu, rs0, 1); rs0 += __shfl_xor_sync(0xffffffffu, rs0, 2);
    rs1 += __shfl_xor_sync(0xffffffffu, rs1, 1); rs1 += __shfl_xor_sync(0xffffffffu, rs1, 2);
    __syncthreads();
    if (tg == 0) { srows[warp * 16 + g] = rs0; srows[warp * 16 + 8 + g] = rs1; }
    __syncthreads();
    if (tid < 128) { float s = srows[tid]; srinv[tid] = (s > 0.f) ? (1.0f / s) : 0.f; }
    __syncthreads();
    const float rinv0 = srinv[warp * 16 + g];
    const float rinv1 = srinv[warp * 16 + 8 + g];

    // =============== PASS 2: normalized att + O ===============
    float o[8][4];
    #pragma unroll
    for (int nt = 0; nt < 8; nt++)
        #pragma unroll
        for (int j = 0; j < 4; j++) o[nt][j] = 0.f;

    for (int t = 0; t < Ss / KT; t++) {
        __syncthreads();
        load_tile(Kg + (size_t)t * KT * Dd, sm, OFF_K, tid, 1.0f);
        load_tile(Vg + (size_t)t * KT * Dd, sm, OFF_V, tid, 1.0f);
        __syncthreads();

        #pragma unroll
        for (int nt = 0; nt < 16; nt++)
            #pragma unroll
            for (int j = 0; j < 4; j++) c[nt][j] = 0.f;

        #pragma unroll
        for (int kc = 0; kc < 4; kc++) {
            uint32_t a[4];
            ldsm4(a, sQb + kc * 32);
            #pragma unroll
            for (int np = 0; np < 8; np++) {
                uint32_t bf[4];
                ldsm4(bf, sKb + (uint32_t)(np * 16 * LDH) * 2 + kc * 32);
                mma16816(c[2 * np],     a, bf[0], bf[1]);
                mma16816(c[2 * np + 1], a, bf[2], bf[3]);
            }
        }

        // epilogue: u = mask ? exp(e)*rinv : 0 ; store att ; keep u in c[]
        const int* mr = Mg + (size_t)qrow * Ss + t * KT + 2 * tg;
        float* ar = attg ? (attg + (size_t)qrow * Ss + t * KT + 2 * tg) : nullptr;
        #pragma unroll
        for (int nt = 0; nt < 16; nt++) {
            int2 m0 = *(const int2*)(mr + 8 * nt);
            int2 m1 = *(const int2*)(mr + 8 * Ss + 8 * nt);
            float u0 = m0.x ? __expf(c[nt][0]) * rinv0 : 0.f;
            float u1 = m0.y ? __expf(c[nt][1]) * rinv0 : 0.f;
            float u2 = m1.x ? __expf(c[nt][2]) * rinv1 : 0.f;
            float u3 = m1.y ? __expf(c[nt][3]) * rinv1 : 0.f;
            if (ar) {
                *(float2*)(ar + 8 * nt)          = make_float2(u0, u1);
                *(float2*)(ar + 8 * Ss + 8 * nt) = make_float2(u2, u3);
            }
            c[nt][0] = u0; c[nt][1] = u1; c[nt][2] = u2; c[nt][3] = u3;
        }

        // PV: A = u (register fragments), B = V via ldmatrix.trans
        #pragma unroll
        for (int kc = 0; kc < 8; kc++) {
            uint32_t a[4];
            a[0] = packh2(c[2 * kc][0],     c[2 * kc][1]);
            a[1] = packh2(c[2 * kc][2],     c[2 * kc][3]);
            a[2] = packh2(c[2 * kc + 1][0], c[2 * kc + 1][1]);
            a[3] = packh2(c[2 * kc + 1][2], c[2 * kc + 1][3]);
            #pragma unroll
            for (int np = 0; np < 4; np++) {
                uint32_t bf[4];
                ldsm4t(bf, sVb + (uint32_t)(kc * 16 * LDH) * 2 + np * 32);
                mma16816(o[2 * np],     a, bf[0], bf[1]);
                mma16816(o[2 * np + 1], a, bf[2], bf[3]);
            }
        }
    }

    // ---- O writeout (already normalized) ----
    if (out) {
        float* og = out + ((size_t)bh * Ss + qrow) * Dd + 2 * tg;
        #pragma unroll
        for (int nt = 0; nt < 8; nt++) {
            *(float2*)(og + 8 * nt)          = make_float2(o[nt][0], o[nt][1]);
            *(float2*)(og + 8 * Dd + 8 * nt) = make_float2(o[nt][2], o[nt][3]);
        }
    }
}

extern "C" void kernel_launch(void* const* d_in, const int* in_sizes, int n_in,
                              void* d_out, int out_size)
{
    (void)in_sizes; (void)n_in;
    const float* Q = (const float*)d_in[0];
    const float* K = (const float*)d_in[1];
    const float* V = (const float*)d_in[2];
    const int*   M = (const int*)d_in[3];

    float* outp = nullptr;
    float* attp = nullptr;
    long long os = (long long)out_size;
    if (os >= OUT_ELEMS + ATT_ELEMS) {
        outp = (float*)d_out;
        attp = (float*)d_out + OUT_ELEMS;
    } else if (os >= ATT_ELEMS) {
        attp = (float*)d_out;
    } else {
        outp = (float*)d_out;
    }

    cudaFuncSetAttribute(attn_kernel, cudaFuncAttributeMaxDynamicSharedMemorySize, SMEM_BYTES);
    dim3 grid(Ss / QT, BH);
    attn_kernel<<<grid, NTH, SMEM_BYTES>>>(Q, K, V, M, outp, attp);
}

// round 4
// speedup vs baseline: 2.5255x; 1.7027x over previous
#include <cuda_runtime.h>
#include <cuda_fp16.h>
#include <cstdint>

#define Ss 2048
#define Dd 64
constexpr int BH  = 32;
constexpr int QT  = 64;            // q rows per CTA
constexpr int KT  = 128;           // k cols per tile
constexpr int NTH = 256;           // 8 warps: 4 row-groups x 2 col-halves
constexpr long long OUT_ELEMS = (long long)BH * Ss * Dd;
constexpr long long ATT_ELEMS = (long long)BH * Ss * (long long)Ss;

// fp16 / uint8 scratch (static device memory — allowed)
__device__ __half g_qh[(size_t)BH * Ss * Dd];    // pre-scaled by 1/8
__device__ __half g_kh[(size_t)BH * Ss * Dd];
__device__ __half g_vh[(size_t)BH * Ss * Dd];
__device__ unsigned char g_m8[(size_t)2 * Ss * Ss];

// smem layout (bytes). Row stride 144B (72 halves / 36 ints) -> conflict-free.
constexpr int OFF_ROWS = 0;                       // 128 floats
constexpr int OFF_RINV = 512;                     // 64 floats
constexpr int OFF_Q    = 1024;                    // 64 x 144
constexpr int KSTG     = 128 * 144;               // 18432
constexpr int OFF_K    = OFF_Q + 64 * 144;        // 10240 ; 2 stages
constexpr int OFF_V    = OFF_K + 2 * KSTG;        // 47104 ; 2 stages
constexpr int MSTG     = 64 * 144;                // 9216
constexpr int OFF_M    = OFF_V + 2 * KSTG;        // 83968 ; 2 stages
constexpr int SMEM_BYTES = OFF_M + 2 * MSTG;      // 102400 -> 2 CTAs/SM

__device__ __forceinline__ uint32_t smem_u32(const void* p) {
    uint32_t a;
    asm("{ .reg .u64 t; cvta.to.shared.u64 t, %1; cvt.u32.u64 %0, t; }" : "=r"(a) : "l"(p));
    return a;
}
__device__ __forceinline__ void ldsm4(uint32_t r[4], uint32_t a) {
    asm volatile("ldmatrix.sync.aligned.m8n8.x4.shared.b16 {%0,%1,%2,%3}, [%4];"
                 : "=r"(r[0]), "=r"(r[1]), "=r"(r[2]), "=r"(r[3]) : "r"(a) : "memory");
}
__device__ __forceinline__ void ldsm4t(uint32_t r[4], uint32_t a) {
    asm volatile("ldmatrix.sync.aligned.m8n8.x4.trans.shared.b16 {%0,%1,%2,%3}, [%4];"
                 : "=r"(r[0]), "=r"(r[1]), "=r"(r[2]), "=r"(r[3]) : "r"(a) : "memory");
}
__device__ __forceinline__ void mma16816(float c[4], const uint32_t a[4], uint32_t b0, uint32_t b1) {
    asm volatile(
        "mma.sync.aligned.m16n8k16.row.col.f32.f16.f16.f32 "
        "{%0,%1,%2,%3}, {%4,%5,%6,%7}, {%8,%9}, {%0,%1,%2,%3};"
        : "+f"(c[0]), "+f"(c[1]), "+f"(c[2]), "+f"(c[3])
        : "r"(a[0]), "r"(a[1]), "r"(a[2]), "r"(a[3]), "r"(b0), "r"(b1));
}
__device__ __forceinline__ uint32_t packh2(float x, float y) {
    __half2 h = __floats2half2_rn(x, y);
    return *(uint32_t*)&h;
}
#define CPA16(dst, src) asm volatile("cp.async.cg.shared.global [%0], [%1], 16;" :: "r"(dst), "l"(src))
#define CP_COMMIT()     asm volatile("cp.async.commit_group;" ::: "memory")
#define CP_WAIT0()      asm volatile("cp.async.wait_group 0;" ::: "memory")

// ---------------- pre-convert kernels ----------------
__global__ void __launch_bounds__(256) cvt_qkv(const float* __restrict__ Q,
                                               const float* __restrict__ K,
                                               const float* __restrict__ V)
{
    const int n4 = (int)((size_t)BH * Ss * Dd / 4);   // 1,048,576 float4 per tensor
    int id = blockIdx.x * 256 + threadIdx.x;
    const float* src; __half* dst; float s;
    int i = id;
    if (id < n4)            { src = Q; dst = g_qh; s = 0.125f; }
    else if (id < 2 * n4)   { src = K; dst = g_kh; s = 1.f; i -= n4; }
    else                    { src = V; dst = g_vh; s = 1.f; i -= 2 * n4; }
    float4 v = ((const float4*)src)[i];
    uint2 u; u.x = packh2(v.x * s, v.y * s); u.y = packh2(v.z * s, v.w * s);
    ((uint2*)dst)[i] = u;
}
__global__ void __launch_bounds__(256) cvt_mask(const int* __restrict__ M)
{
    int i = blockIdx.x * 256 + threadIdx.x;           // 2,097,152 int4
    int4 m = ((const int4*)M)[i];
    uchar4 o; o.x = (unsigned char)m.x; o.y = (unsigned char)m.y;
    o.z = (unsigned char)m.z; o.w = (unsigned char)m.w;
    ((uchar4*)g_m8)[i] = o;
}

extern __shared__ __align__(16) char sm[];

__global__ void __launch_bounds__(NTH, 2)
attn_kernel(float* __restrict__ out, float* __restrict__ att)
{
    const int tid  = threadIdx.x;
    const int lane = tid & 31;
    const int warp = tid >> 5;
    const int g    = lane >> 2;
    const int tg   = lane & 3;
    const int lm   = lane >> 3;
    const int ll   = lane & 7;
    const int rgrp = warp & 3;         // q-row group (16 rows)
    const int h    = warp >> 2;        // k-col half (64 cols)

    const int q0 = blockIdx.x * QT;
    const int bh = blockIdx.y;
    const int b  = bh >> 4;

    const uint32_t smb = smem_u32(sm);
    float* srows = (float*)(sm + OFF_ROWS);
    float* srinv = (float*)(sm + OFF_RINV);

    const __half* qsrc = g_qh + ((size_t)bh * Ss + q0) * Dd;
    const __half* ksrc = g_kh + (size_t)bh * Ss * Dd;
    const __half* vsrc = g_vh + (size_t)bh * Ss * Dd;
    const unsigned char* msrc = g_m8 + (size_t)b * Ss * Ss + (size_t)q0 * Ss;
    float* attg = att ? (att + (size_t)bh * Ss * (size_t)Ss) : nullptr;

    // fragment address bases
    const uint32_t qfr = smb + OFF_Q + (uint32_t)((rgrp * 16 + (lm & 1) * 8 + ll) * 144 + ((lm >> 1) * 8) * 2);
    const uint32_t kfr = smb + OFF_K + (uint32_t)((h * 64 + (lm >> 1) * 8 + ll) * 144 + ((lm & 1) * 8) * 2);
    const uint32_t vfr = smb + OFF_V + (uint32_t)((h * 64 + (lm & 1) * 8 + ll) * 144 + ((lm >> 1) * 8) * 2);
    const int moff0 = (rgrp * 16 + g) * 144 + h * 64 + 2 * tg;

    // ---- prologue: Q + K(0) + M(0) via cp.async ----
    #pragma unroll
    for (int i = 0; i < 2; i++) {                    // Q: 512 chunks
        int idx = tid + i * NTH; int r = idx >> 3, c = idx & 7;
        CPA16(smb + OFF_Q + r * 144 + c * 16, qsrc + r * 64 + c * 8);
    }
    #pragma unroll
    for (int i = 0; i < 4; i++) {                    // K tile 0
        int idx = tid + i * NTH; int r = idx >> 3, c = idx & 7;
        CPA16(smb + OFF_K + r * 144 + c * 16, ksrc + (size_t)r * 64 + c * 8);
    }
    #pragma unroll
    for (int i = 0; i < 2; i++) {                    // M tile 0
        int idx = tid + i * NTH; int r = idx >> 3, c = idx & 7;
        CPA16(smb + OFF_M + r * 144 + c * 16, msrc + (size_t)r * Ss + c * 16);
    }
    CP_COMMIT();
    CP_WAIT0();
    __syncthreads();

    // Q fragments once (persist in regs)
    uint32_t aQ[4][4];
    #pragma unroll
    for (int kc = 0; kc < 4; kc++) ldsm4(aQ[kc], qfr + kc * 32);

    float c[8][4];

    // ================= PASS 1: row sums =================
    float rs0 = 0.f, rs1 = 0.f;
    for (int t = 0; t < Ss / KT; t++) {
        const int stg = t & 1;
        if (t + 1 < Ss / KT) {
            const int ns = (t + 1) & 1;
            #pragma unroll
            for (int i = 0; i < 4; i++) {
                int idx = tid + i * NTH; int r = idx >> 3, cc = idx & 7;
                CPA16(smb + OFF_K + ns * KSTG + r * 144 + cc * 16,
                      ksrc + ((size_t)(t + 1) * KT + r) * 64 + cc * 8);
            }
            #pragma unroll
            for (int i = 0; i < 2; i++) {
                int idx = tid + i * NTH; int r = idx >> 3, cc = idx & 7;
                CPA16(smb + OFF_M + ns * MSTG + r * 144 + cc * 16,
                      msrc + (size_t)r * Ss + (t + 1) * KT + cc * 16);
            }
            CP_COMMIT();
        }

        #pragma unroll
        for (int nt = 0; nt < 8; nt++)
            #pragma unroll
            for (int j = 0; j < 4; j++) c[nt][j] = 0.f;

        #pragma unroll
        for (int kc = 0; kc < 4; kc++)
            #pragma unroll
            for (int np = 0; np < 4; np++) {
                uint32_t bf[4];
                ldsm4(bf, kfr + stg * KSTG + np * 2304 + kc * 32);
                mma16816(c[2 * np],     aQ[kc], bf[0], bf[1]);
                mma16816(c[2 * np + 1], aQ[kc], bf[2], bf[3]);
            }

        #pragma unroll
        for (int nt = 0; nt < 8; nt++) {
            uint16_t m0 = *(const uint16_t*)(sm + OFF_M + stg * MSTG + moff0 + 8 * nt);
            uint16_t m1 = *(const uint16_t*)(sm + OFF_M + stg * MSTG + moff0 + 8 * 144 + 8 * nt);
            rs0 += ((m0 & 0xFF) ? __expf(c[nt][0]) : 0.f) + ((m0 >> 8) ? __expf(c[nt][1]) : 0.f);
            rs1 += ((m1 & 0xFF) ? __expf(c[nt][2]) : 0.f) + ((m1 >> 8) ? __expf(c[nt][3]) : 0.f);
        }

        if (t + 1 < Ss / KT) { CP_WAIT0(); __syncthreads(); }
    }

    // reduce: quad, then halves across h
    rs0 += __shfl_xor_sync(0xffffffffu, rs0, 1); rs0 += __shfl_xor_sync(0xffffffffu, rs0, 2);
    rs1 += __shfl_xor_sync(0xffffffffu, rs1, 1); rs1 += __shfl_xor_sync(0xffffffffu, rs1, 2);
    __syncthreads();
    if (tg == 0) { srows[h * 64 + rgrp * 16 + g] = rs0; srows[h * 64 + rgrp * 16 + 8 + g] = rs1; }
    __syncthreads();
    if (tid < 64) {
        float s = srows[tid] + srows[64 + tid];
        srinv[tid] = (s > 0.f) ? (1.0f / s) : 0.f;
    }
    __syncthreads();
    const float rinv0 = srinv[rgrp * 16 + g];
    const float rinv1 = srinv[rgrp * 16 + 8 + g];

    // ================= PASS 2: normalized att + O =================
    float o[8][4];
    #pragma unroll
    for (int nt = 0; nt < 8; nt++)
        #pragma unroll
        for (int j = 0; j < 4; j++) o[nt][j] = 0.f;

    // prologue tile 0 (K,V,M)
    #pragma unroll
    for (int i = 0; i < 4; i++) {
        int idx = tid + i * NTH; int r = idx >> 3, cc = idx & 7;
        CPA16(smb + OFF_K + r * 144 + cc * 16, ksrc + (size_t)r * 64 + cc * 8);
        CPA16(smb + OFF_V + r * 144 + cc * 16, vsrc + (size_t)r * 64 + cc * 8);
    }
    #pragma unroll
    for (int i = 0; i < 2; i++) {
        int idx = tid + i * NTH; int r = idx >> 3, cc = idx & 7;
        CPA16(smb + OFF_M + r * 144 + cc * 16, msrc + (size_t)r * Ss + cc * 16);
    }
    CP_COMMIT();
    CP_WAIT0();
    __syncthreads();

    for (int t = 0; t < Ss / KT; t++) {
        const int stg = t & 1;
        if (t + 1 < Ss / KT) {
            const int ns = (t + 1) & 1;
            #pragma unroll
            for (int i = 0; i < 4; i++) {
                int idx = tid + i * NTH; int r = idx >> 3, cc = idx & 7;
                CPA16(smb + OFF_K + ns * KSTG + r * 144 + cc * 16,
                      ksrc + ((size_t)(t + 1) * KT + r) * 64 + cc * 8);
                CPA16(smb + OFF_V + ns * KSTG + r * 144 + cc * 16,
                      vsrc + ((size_t)(t + 1) * KT + r) * 64 + cc * 8);
            }
            #pragma unroll
            for (int i = 0; i < 2; i++) {
                int idx = tid + i * NTH; int r = idx >> 3, cc = idx & 7;
                CPA16(smb + OFF_M + ns * MSTG + r * 144 + cc * 16,
                      msrc + (size_t)r * Ss + (t + 1) * KT + cc * 16);
            }
            CP_COMMIT();
        }

        #pragma unroll
        for (int nt = 0; nt < 8; nt++)
            #pragma unroll
            for (int j = 0; j < 4; j++) c[nt][j] = 0.f;

        #pragma unroll
        for (int kc = 0; kc < 4; kc++)
            #pragma unroll
            for (int np = 0; np < 4; np++) {
                uint32_t bf[4];
                ldsm4(bf, kfr + stg * KSTG + np * 2304 + kc * 32);
                mma16816(c[2 * np],     aQ[kc], bf[0], bf[1]);
                mma16816(c[2 * np + 1], aQ[kc], bf[2], bf[3]);
            }

        // epilogue: u = mask ? exp(e)*rinv : 0 ; store att ; keep u in c[]
        const int qrow = q0 + rgrp * 16 + g;
        float* ar = attg ? (attg + (size_t)qrow * Ss + t * KT + h * 64 + 2 * tg) : nullptr;
        #pragma unroll
        for (int nt = 0; nt < 8; nt++) {
            uint16_t m0 = *(const uint16_t*)(sm + OFF_M + stg * MSTG + moff0 + 8 * nt);
            uint16_t m1 = *(const uint16_t*)(sm + OFF_M + stg * MSTG + moff0 + 8 * 144 + 8 * nt);
            float u0 = (m0 & 0xFF) ? __expf(c[nt][0]) * rinv0 : 0.f;
            float u1 = (m0 >> 8)   ? __expf(c[nt][1]) * rinv0 : 0.f;
            float u2 = (m1 & 0xFF) ? __expf(c[nt][2]) * rinv1 : 0.f;
            float u3 = (m1 >> 8)   ? __expf(c[nt][3]) * rinv1 : 0.f;
            if (ar) {
                *(float2*)(ar + 8 * nt)          = make_float2(u0, u1);
                *(float2*)(ar + 8 * Ss + 8 * nt) = make_float2(u2, u3);
            }
            c[nt][0] = u0; c[nt][1] = u1; c[nt][2] = u2; c[nt][3] = u3;
        }

        // PV: A = u fragments, B = V^T via ldmatrix.trans
        #pragma unroll
        for (int kc = 0; kc < 4; kc++) {
            uint32_t a[4];
            a[0] = packh2(c[2 * kc][0],     c[2 * kc][1]);
            a[1] = packh2(c[2 * kc][2],     c[2 * kc][3]);
            a[2] = packh2(c[2 * kc + 1][0], c[2 * kc + 1][1]);
            a[3] = packh2(c[2 * kc + 1][2], c[2 * kc + 1][3]);
            #pragma unroll
            for (int np = 0; np < 4; np++) {
                uint32_t bf[4];
                ldsm4t(bf, vfr + stg * KSTG + kc * 2304 + np * 32);
                mma16816(o[2 * np],     a, bf[0], bf[1]);
                mma16816(o[2 * np + 1], a, bf[2], bf[3]);
            }
        }

        if (t + 1 < Ss / KT) { CP_WAIT0(); __syncthreads(); }
    }

    // ---- combine the two k-halves of O via smem, write out ----
    __syncthreads();
    float* ostage = (float*)(sm + OFF_K);            // 64 x 68 floats
    if (h == 1) {
        #pragma unroll
        for (int nt = 0; nt < 8; nt++) {
            *(float2*)(ostage + (rgrp * 16 + g) * 68 + 8 * nt + 2 * tg)     = make_float2(o[nt][0], o[nt][1]);
            *(float2*)(ostage + (rgrp * 16 + 8 + g) * 68 + 8 * nt + 2 * tg) = make_float2(o[nt][2], o[nt][3]);
        }
    }
    __syncthreads();
    if (out && h == 0) {
        float* og = out + ((size_t)bh * Ss + q0 + rgrp * 16 + g) * Dd + 2 * tg;
        #pragma unroll
        for (int nt = 0; nt < 8; nt++) {
            float2 s0 = *(float2*)(ostage + (rgrp * 16 + g) * 68 + 8 * nt + 2 * tg);
            float2 s1 = *(float2*)(ostage + (rgrp * 16 + 8 + g) * 68 + 8 * nt + 2 * tg);
            *(float2*)(og + 8 * nt)          = make_float2(o[nt][0] + s0.x, o[nt][1] + s0.y);
            *(float2*)(og + 8 * Dd + 8 * nt) = make_float2(o[nt][2] + s1.x, o[nt][3] + s1.y);
        }
    }
}

extern "C" void kernel_launch(void* const* d_in, const int* in_sizes, int n_in,
                              void* d_out, int out_size)
{
    (void)in_sizes; (void)n_in;
    const float* Q = (const float*)d_in[0];
    const float* K = (const float*)d_in[1];
    const float* V = (const float*)d_in[2];
    const int*   M = (const int*)d_in[3];

    float* outp = nullptr;
    float* attp = nullptr;
    long long os = (long long)out_size;
    if (os >= OUT_ELEMS + ATT_ELEMS) {
        outp = (float*)d_out;
        attp = (float*)d_out + OUT_ELEMS;
    } else if (os >= ATT_ELEMS) {
        attp = (float*)d_out;
    } else {
        outp = (float*)d_out;
    }

    cvt_qkv<<<3 * 4096 * 1024 / 4 / 256, 256>>>(Q, K, V);   // 12288 blocks
    cvt_mask<<<(2 * Ss * Ss / 4) / 256, 256>>>(M);          // 8192 blocks

    cudaFuncSetAttribute(attn_kernel, cudaFuncAttributeMaxDynamicSharedMemorySize, SMEM_BYTES);
    dim3 grid(Ss / QT, BH);
    attn_kernel<<<grid, NTH, SMEM_BYTES>>>(outp, attp);
}